// round 4
// baseline (speedup 1.0000x reference)
#include <cuda_runtime.h>
#include <cuda_bf16.h>
#include <math.h>

#define D   64
#define NC  10
#define NS  4096

// final cluster centers handed from kernel A to kernel B
__device__ float g_cc[NC * D];

// ---------------------------------------------------------------------------
// Kernel A helpers: all run with 640 threads (one block).
// ---------------------------------------------------------------------------

// Stage 64*INNER contiguous floats (rows [r0, r0+CH) of W[.. ][INNER]) into
// swb with row stride INNER+4 (keeps float4 alignment AND conflict-free
// column-parallel reads: bank = (4*ob + j) % 32, distinct within 8-lane phase).
template<int INNER>
__device__ __forceinline__ void stage_chunk(const float* __restrict__ W, float* swb,
                                            int r0, int t) {
    const float4* g4 = (const float4*)(W + (size_t)r0 * INNER);
    #pragma unroll 1
    for (int f = t; f < 1024; f += 640) {           // 4096 floats per chunk
        float4 v = g4[f];
        int r = (4 * f) / INNER;
        int c = (4 * f) % INNER;
        *(float4*)(swb + r * (INNER + 4) + c) = v;
    }
}

// out[NC][ODIM] = act( X[NC][INNER] @ W[ODIM][INNER]^T + B )
// chunked over output rows so the smem weight buffer stays <= 4352 floats.
template<int ODIM, int INNER, int ACT>
__device__ __forceinline__ void mm(const float* __restrict__ X,
                                   const float* __restrict__ W,
                                   const float* __restrict__ B,
                                   float* __restrict__ out,
                                   float* swb, int t) {
    constexpr int CH  = 4096 / INNER;   // 64 (INNER=64) or 32 (INNER=128)
    constexpr int STR = INNER + 4;
    for (int r0 = 0; r0 < ODIM; r0 += CH) {
        __syncthreads();                // protect swb from previous readers
        stage_chunk<INNER>(W, swb, r0, t);
        __syncthreads();
        if (t < NC * CH) {
            int n  = t / CH;
            int ob = t % CH;
            const float* x = X + n * INNER;       // warp-uniform -> broadcast
            const float* w = swb + ob * STR;      // conflict-free across lanes
            float ax = 0.f, ay = 0.f, az = 0.f, aw = 0.f;
            #pragma unroll
            for (int j = 0; j < INNER; j += 4) {
                float4 xv = *(const float4*)(x + j);
                float4 wv = *(const float4*)(w + j);
                ax = fmaf(wv.x, xv.x, ax);
                ay = fmaf(wv.y, xv.y, ay);
                az = fmaf(wv.z, xv.z, az);
                aw = fmaf(wv.w, xv.w, aw);
            }
            int o = r0 + ob;
            float acc = (ax + ay) + (az + aw) + B[o];
            if (ACT) acc = fmaxf(acc, 0.f);
            out[n * ODIM + o] = acc;
        }
    }
    __syncthreads();
}

// layernorm over last dim (population variance), out = (x-m)/sqrt(v+eps)*g+b
__device__ __forceinline__ void ln640(const float* __restrict__ X,
                                      const float* __restrict__ gma,
                                      const float* __restrict__ bta,
                                      float* __restrict__ out,
                                      float* sred, int t) {
    if (t < NC) {
        const float* r = X + t * D;
        float s = 0.f, s2 = 0.f;
        #pragma unroll
        for (int j = 0; j < D; j++) { float v = r[j]; s += v; s2 += v * v; }
        float m   = s * (1.f / D);
        float var = s2 * (1.f / D) - m * m;
        sred[t]      = m;
        sred[16 + t] = rsqrtf(var + 1e-5f);
    }
    __syncthreads();
    int n  = t >> 6;
    int ii = t & 63;
    out[t] = (X[t] - sred[n]) * sred[16 + n] * gma[ii] + bta[ii];
    __syncthreads();
}

// ---------------------------------------------------------------------------
// Kernel A: 3 iterations of slot attention + GRU + residual MLP on [10,64]
// ---------------------------------------------------------------------------
__global__ void __launch_bounds__(640)
iter_kernel(const float* __restrict__ cc0,
            const float* __restrict__ Wk, const float* __restrict__ bk,
            const float* __restrict__ Wq, const float* __restrict__ bq,
            const float* __restrict__ Wv, const float* __restrict__ bv,
            const float* __restrict__ cc_g, const float* __restrict__ cc_b,
            const float* __restrict__ W_ih, const float* __restrict__ W_hh,
            const float* __restrict__ b_ih, const float* __restrict__ b_hh,
            const float* __restrict__ ln_g, const float* __restrict__ ln_b,
            const float* __restrict__ W1, const float* __restrict__ b1,
            const float* __restrict__ W2, const float* __restrict__ b2) {
    __shared__ float scc[NC * D];      // current cc
    __shared__ float sk [NC * D];
    __shared__ float sv [NC * D];
    __shared__ float sq [NC * D];
    __shared__ float sxu[NC * D];      // LN output / updates (reused)
    __shared__ float sgi[NC * 192];    // gi / mlp hidden h1 (reused)
    __shared__ float sgh[NC * 192];    // gh / mlp output (reused)
    __shared__ float sattn[128];       // 10x10 attn
    __shared__ float sred[32];         // mean / rstd
    __shared__ float swb[64 * 68];     // staged weight chunk (4352 floats)

    const int t  = threadIdx.x;
    const int n  = t >> 6;
    const int ii = t & 63;

    scc[t] = cc0[t];
    __syncthreads();

    // k, v from the ORIGINAL cluster centers
    mm<64, 64, 0>(scc, Wk, bk, sk, swb, t);
    mm<64, 64, 0>(scc, Wv, bv, sv, swb, t);

    for (int it = 0; it < 3; it++) {
        // ---- q = LN(cc; cc_g, cc_b) @ Wq^T + bq
        ln640(scc, cc_g, cc_b, sxu, sred, t);
        mm<64, 64, 0>(sxu, Wq, bq, sq, swb, t);

        // ---- attn logits: attn[nn][m] = k[nn].q[m] / 8
        if (t < 100) {
            int an = t / 10, am = t % 10;
            const float* kr = sk + an * D;
            const float* qr = sq + am * D;
            float a = 0.f;
            #pragma unroll
            for (int j = 0; j < D; j++) a = fmaf(kr[j], qr[j], a);
            sattn[an * 10 + am] = a * 0.125f;
        }
        __syncthreads();
        // softmax over axis 0 (over nn), column m = t
        if (t < 10) {
            float mx = -1e30f;
            #pragma unroll
            for (int a = 0; a < 10; a++) mx = fmaxf(mx, sattn[a * 10 + t]);
            float ss = 0.f;
            #pragma unroll
            for (int a = 0; a < 10; a++) {
                float e = expf(sattn[a * 10 + t] - mx);
                sattn[a * 10 + t] = e;
                ss += e;
            }
            float inv = 1.f / ss;
            #pragma unroll
            for (int a = 0; a < 10; a++)
                sattn[a * 10 + t] = sattn[a * 10 + t] * inv + 1e-8f;
        }
        __syncthreads();
        // renormalize rows (axis -1, over m), row nn = t
        if (t < 10) {
            float ss = 0.f;
            #pragma unroll
            for (int m = 0; m < 10; m++) ss += sattn[t * 10 + m];
            float inv = 1.f / ss;
            #pragma unroll
            for (int m = 0; m < 10; m++) sattn[t * 10 + m] *= inv;
        }
        __syncthreads();
        // updates = attn @ v  -> sxu
        {
            float u = 0.f;
            #pragma unroll
            for (int m = 0; m < 10; m++)
                u = fmaf(sattn[n * 10 + m], sv[m * D + ii], u);
            sxu[t] = u;
        }
        __syncthreads();

        // ---- GRU gates
        mm<192, 64, 0>(sxu, W_ih, b_ih, sgi, swb, t);   // gi from updates
        mm<192, 64, 0>(scc, W_hh, b_hh, sgh, swb, t);   // gh from cc_prev
        {
            float ir  = sgi[n * 192 + ii];
            float iz  = sgi[n * 192 + 64 + ii];
            float in_ = sgi[n * 192 + 128 + ii];
            float hr  = sgh[n * 192 + ii];
            float hz  = sgh[n * 192 + 64 + ii];
            float hn  = sgh[n * 192 + 128 + ii];
            float r = 1.f / (1.f + expf(-(ir + hr)));
            float z = 1.f / (1.f + expf(-(iz + hz)));
            float nn = tanhf(in_ + r * hn);
            scc[t] = (1.f - z) * nn + z * scc[t];
        }
        __syncthreads();

        // ---- residual MLP: cc += relu(LN(cc) @ W1^T + b1) @ W2^T + b2
        ln640(scc, ln_g, ln_b, sxu, sred, t);
        mm<128, 64, 1>(sxu, W1, b1, sgi, swb, t);       // h1 [10,128]
        mm<64, 128, 0>(sgi, W2, b2, sgh, swb, t);       // delta [10,64]
        scc[t] += sgh[t];
        __syncthreads();
    }

    g_cc[t] = scc[t];
}

// ---------------------------------------------------------------------------
// Kernel B: per-slot 2-layer MLP + max over the 10 clusters. One block/slot.
// thread (i = t&63, g = t>>6): output dim i, clusters [5g, 5g+5).
// ---------------------------------------------------------------------------
__global__ void __launch_bounds__(128)
mlp_kernel(const float* __restrict__ Wa, const float* __restrict__ ba,
           const float* __restrict__ Wb, const float* __restrict__ bb,
           float* __restrict__ out) {
    __shared__ float sWa[64 * 68];
    __shared__ float sWb[64 * 68];
    __shared__ float scc[NC * D];
    __shared__ float sh [NC * D];
    __shared__ float smax[128];

    const int s = blockIdx.x;
    const int t = threadIdx.x;
    const int i = t & 63;
    const int g = t >> 6;
    const size_t base = (size_t)s * (D * D);

    // stage both weight tiles (coalesced float4, 16 independent LDGs/thread)
    const float4* ga = (const float4*)(Wa + base);
    const float4* gb = (const float4*)(Wb + base);
    #pragma unroll
    for (int p = 0; p < 8; p++) {
        int f = t + p * 128;
        int r = f >> 4;
        int c = (f & 15) << 2;
        *(float4*)(sWa + r * 68 + c) = ga[f];
        *(float4*)(sWb + r * 68 + c) = gb[f];
    }
    for (int p = t; p < NC * D; p += 128) scc[p] = g_cc[p];
    __syncthreads();

    // ---- stage 1: h[nn][i] = relu(Wa[i,:] . cc[nn,:] + ba[i]) for 5 nn
    {
        const float* wr = sWa + i * 68;
        const float* cb = scc + g * 5 * D;
        float a0 = 0.f, a1 = 0.f, a2 = 0.f, a3 = 0.f, a4 = 0.f;
        #pragma unroll
        for (int j = 0; j < D; j += 4) {
            float4 w  = *(const float4*)(wr + j);
            float4 c0 = *(const float4*)(cb + j);
            float4 c1 = *(const float4*)(cb + D + j);
            float4 c2 = *(const float4*)(cb + 2 * D + j);
            float4 c3 = *(const float4*)(cb + 3 * D + j);
            float4 c4 = *(const float4*)(cb + 4 * D + j);
            a0 = fmaf(w.x, c0.x, fmaf(w.y, c0.y, fmaf(w.z, c0.z, fmaf(w.w, c0.w, a0))));
            a1 = fmaf(w.x, c1.x, fmaf(w.y, c1.y, fmaf(w.z, c1.z, fmaf(w.w, c1.w, a1))));
            a2 = fmaf(w.x, c2.x, fmaf(w.y, c2.y, fmaf(w.z, c2.z, fmaf(w.w, c2.w, a2))));
            a3 = fmaf(w.x, c3.x, fmaf(w.y, c3.y, fmaf(w.z, c3.z, fmaf(w.w, c3.w, a3))));
            a4 = fmaf(w.x, c4.x, fmaf(w.y, c4.y, fmaf(w.z, c4.z, fmaf(w.w, c4.w, a4))));
        }
        float bav = ba[(s << 6) + i];
        int n0 = g * 5;
        sh[(n0 + 0) * D + i] = fmaxf(a0 + bav, 0.f);
        sh[(n0 + 1) * D + i] = fmaxf(a1 + bav, 0.f);
        sh[(n0 + 2) * D + i] = fmaxf(a2 + bav, 0.f);
        sh[(n0 + 3) * D + i] = fmaxf(a3 + bav, 0.f);
        sh[(n0 + 4) * D + i] = fmaxf(a4 + bav, 0.f);
    }
    __syncthreads();

    // ---- stage 2: out[nn][i] = Wb[i,:] . h[nn,:] + bb[i], max over nn
    {
        const float* wr = sWb + i * 68;
        const float* hb = sh + g * 5 * D;
        float a0 = 0.f, a1 = 0.f, a2 = 0.f, a3 = 0.f, a4 = 0.f;
        #pragma unroll
        for (int j = 0; j < D; j += 4) {
            float4 w  = *(const float4*)(wr + j);
            float4 c0 = *(const float4*)(hb + j);
            float4 c1 = *(const float4*)(hb + D + j);
            float4 c2 = *(const float4*)(hb + 2 * D + j);
            float4 c3 = *(const float4*)(hb + 3 * D + j);
            float4 c4 = *(const float4*)(hb + 4 * D + j);
            a0 = fmaf(w.x, c0.x, fmaf(w.y, c0.y, fmaf(w.z, c0.z, fmaf(w.w, c0.w, a0))));
            a1 = fmaf(w.x, c1.x, fmaf(w.y, c1.y, fmaf(w.z, c1.z, fmaf(w.w, c1.w, a1))));
            a2 = fmaf(w.x, c2.x, fmaf(w.y, c2.y, fmaf(w.z, c2.z, fmaf(w.w, c2.w, a2))));
            a3 = fmaf(w.x, c3.x, fmaf(w.y, c3.y, fmaf(w.z, c3.z, fmaf(w.w, c3.w, a3))));
            a4 = fmaf(w.x, c4.x, fmaf(w.y, c4.y, fmaf(w.z, c4.z, fmaf(w.w, c4.w, a4))));
        }
        float bbv = bb[(s << 6) + i];
        float mx = fmaxf(fmaxf(fmaxf(a0, a1), fmaxf(a2, a3)), a4) + bbv;
        smax[t] = mx;
    }
    __syncthreads();
    if (g == 0) out[(s << 6) + i] = fmaxf(smax[i], smax[64 + i]);
}

// ---------------------------------------------------------------------------
extern "C" void kernel_launch(void* const* d_in, const int* in_sizes, int n_in,
                              void* d_out, int out_size) {
    const float* cc0  = (const float*)d_in[0];
    const float* Wk   = (const float*)d_in[1];
    const float* bk   = (const float*)d_in[2];
    const float* Wq   = (const float*)d_in[3];
    const float* bq   = (const float*)d_in[4];
    const float* Wv   = (const float*)d_in[5];
    const float* bv   = (const float*)d_in[6];
    const float* cc_g = (const float*)d_in[7];
    const float* cc_b = (const float*)d_in[8];
    const float* W_ih = (const float*)d_in[9];
    const float* W_hh = (const float*)d_in[10];
    const float* b_ih = (const float*)d_in[11];
    const float* b_hh = (const float*)d_in[12];
    const float* ln_g = (const float*)d_in[13];
    const float* ln_b = (const float*)d_in[14];
    const float* W1   = (const float*)d_in[15];
    const float* b1   = (const float*)d_in[16];
    const float* W2   = (const float*)d_in[17];
    const float* b2   = (const float*)d_in[18];
    const float* Wa   = (const float*)d_in[19];
    const float* ba   = (const float*)d_in[20];
    const float* Wb   = (const float*)d_in[21];
    const float* bb   = (const float*)d_in[22];
    float* out = (float*)d_out;

    iter_kernel<<<1, 640>>>(cc0, Wk, bk, Wq, bq, Wv, bv, cc_g, cc_b,
                            W_ih, W_hh, b_ih, b_hh, ln_g, ln_b,
                            W1, b1, W2, b2);
    mlp_kernel<<<NS, 128>>>(Wa, ba, Wb, bb, out);
}

// round 7
// speedup vs baseline: 1.6792x; 1.6792x over previous
#include <cuda_runtime.h>
#include <cuda_bf16.h>
#include <math.h>
#include <cstdint>

#define D   64
#define NC  10
#define NS  4096

// final cluster centers handed from kernel A to kernel B
__device__ __align__(16) float g_cc[NC * D];

// ---------------------------------------------------------------------------
// Kernel A: all weights staged to shared memory ONCE, then 3 iterations run
// entirely from smem. 640 threads, 1 block.
// Dynamic smem layout (floats):
//   wq   [64 x68]  @ 0       (4352)
//   wih  [192x68]  @ 4352    (13056)
//   whh  [192x68]  @ 17408   (13056)
//   w1   [128x68]  @ 30464   (8704)   (also temp for Wk)
//   w2   [64 x132] @ 39168   (8448)   (also temp for Wv)
//   scc @47616, sk @48256, sv @48896, sq @49536, sxu @50176 (640 each)
//   sgi @50816 (1920), sgh @52736 (1920), sattn @54656 (128), sred @54784 (32)
// total 54816 floats = 219264 bytes
// ---------------------------------------------------------------------------
#define SMEM_A_FLOATS 54816
#define SMEM_A_BYTES  (SMEM_A_FLOATS * 4)

// stage W[R][C] (row-major, contiguous) into s with row stride C+4 (keeps
// float4 alignment + conflict-free column-parallel float4 reads)
template<int R, int C>
__device__ __forceinline__ void stageW(const float* __restrict__ W, float* s, int t) {
    const float4* g4 = (const float4*)W;
    constexpr int NF4 = R * C / 4;
    #pragma unroll 1
    for (int f = t; f < NF4; f += 640) {
        float4 v = g4[f];
        int r = (4 * f) / C;
        int c = (4 * f) % C;
        *(float4*)(s + r * (C + 4) + c) = v;
    }
}

// out[n][o] = act( X[n][:] . sW[o][:] + B[o] )  for n in [n0, n0+5)
// thread t < ODIM*2: o = t % ODIM, n0 = (t/ODIM)*5.  Weight row read once,
// reused for 5 clusters (X reads are warp-uniform broadcasts).
template<int ODIM, int INNER, int ACT>
__device__ __forceinline__ void mmr(const float* __restrict__ X,
                                    const float* __restrict__ sW,
                                    const float* __restrict__ B,
                                    float* __restrict__ out, int t) {
    constexpr int STR = INNER + 4;
    if (t < ODIM * 2) {
        int o  = t % ODIM;
        int n0 = (t / ODIM) * 5;
        const float* w = sW + o * STR;
        float a0 = 0.f, a1 = 0.f, a2 = 0.f, a3 = 0.f, a4 = 0.f;
        const float* xb = X + n0 * INNER;
        #pragma unroll
        for (int j = 0; j < INNER; j += 4) {
            float4 wv = *(const float4*)(w + j);
            float4 x0 = *(const float4*)(xb + j);
            float4 x1 = *(const float4*)(xb + INNER + j);
            float4 x2 = *(const float4*)(xb + 2 * INNER + j);
            float4 x3 = *(const float4*)(xb + 3 * INNER + j);
            float4 x4 = *(const float4*)(xb + 4 * INNER + j);
            a0 = fmaf(wv.x, x0.x, fmaf(wv.y, x0.y, fmaf(wv.z, x0.z, fmaf(wv.w, x0.w, a0))));
            a1 = fmaf(wv.x, x1.x, fmaf(wv.y, x1.y, fmaf(wv.z, x1.z, fmaf(wv.w, x1.w, a1))));
            a2 = fmaf(wv.x, x2.x, fmaf(wv.y, x2.y, fmaf(wv.z, x2.z, fmaf(wv.w, x2.w, a2))));
            a3 = fmaf(wv.x, x3.x, fmaf(wv.y, x3.y, fmaf(wv.z, x3.z, fmaf(wv.w, x3.w, a3))));
            a4 = fmaf(wv.x, x4.x, fmaf(wv.y, x4.y, fmaf(wv.z, x4.z, fmaf(wv.w, x4.w, a4))));
        }
        float bo = B[o];
        float r0 = a0 + bo, r1 = a1 + bo, r2 = a2 + bo, r3 = a3 + bo, r4 = a4 + bo;
        if (ACT) {
            r0 = fmaxf(r0, 0.f); r1 = fmaxf(r1, 0.f); r2 = fmaxf(r2, 0.f);
            r3 = fmaxf(r3, 0.f); r4 = fmaxf(r4, 0.f);
        }
        out[(n0 + 0) * ODIM + o] = r0;
        out[(n0 + 1) * ODIM + o] = r1;
        out[(n0 + 2) * ODIM + o] = r2;
        out[(n0 + 3) * ODIM + o] = r3;
        out[(n0 + 4) * ODIM + o] = r4;
    }
}

// layernorm over last dim, warp-shuffle reduction (10 warps of 320 threads)
__device__ __forceinline__ void lnw(const float* __restrict__ X,
                                    const float* __restrict__ gma,
                                    const float* __restrict__ bta,
                                    float* __restrict__ out,
                                    float* sred, int t) {
    if (t < 320) {
        int w = t >> 5, l = t & 31;
        float v0 = X[w * 64 + l], v1 = X[w * 64 + 32 + l];
        float s = v0 + v1, s2 = v0 * v0 + v1 * v1;
        #pragma unroll
        for (int off = 16; off; off >>= 1) {
            s  += __shfl_xor_sync(0xffffffffu, s, off);
            s2 += __shfl_xor_sync(0xffffffffu, s2, off);
        }
        if (l == 0) {
            float m = s * (1.f / 64.f);
            sred[w]      = m;
            sred[16 + w] = rsqrtf(s2 * (1.f / 64.f) - m * m + 1e-5f);
        }
    }
    __syncthreads();
    int n = t >> 6, ii = t & 63;
    out[t] = (X[t] - sred[n]) * sred[16 + n] * gma[ii] + bta[ii];
    __syncthreads();
}

__global__ void __launch_bounds__(640)
iter_kernel(const float* __restrict__ cc0,
            const float* __restrict__ Wk, const float* __restrict__ bk,
            const float* __restrict__ Wq, const float* __restrict__ bq,
            const float* __restrict__ Wv, const float* __restrict__ bv,
            const float* __restrict__ cc_g, const float* __restrict__ cc_b,
            const float* __restrict__ W_ih, const float* __restrict__ W_hh,
            const float* __restrict__ b_ih, const float* __restrict__ b_hh,
            const float* __restrict__ ln_g, const float* __restrict__ ln_b,
            const float* __restrict__ W1, const float* __restrict__ b1,
            const float* __restrict__ W2, const float* __restrict__ b2) {
    extern __shared__ float sm[];
    float* swq  = sm;
    float* swih = sm + 4352;
    float* swhh = sm + 17408;
    float* sw1  = sm + 30464;
    float* sw2  = sm + 39168;
    float* scc  = sm + 47616;
    float* sk   = sm + 48256;
    float* sv   = sm + 48896;
    float* sq   = sm + 49536;
    float* sxu  = sm + 50176;
    float* sgi  = sm + 50816;
    float* sgh  = sm + 52736;
    float* sattn= sm + 54656;
    float* sred = sm + 54784;

    const int t  = threadIdx.x;
    const int n  = t >> 6;
    const int ii = t & 63;

    scc[t] = cc0[t];
    // temp-stage Wk -> sw1 buffer, Wv -> sw2 buffer
    stageW<64, 64>(Wk, sw1, t);
    stageW<64, 64>(Wv, sw2, t);
    __syncthreads();

    // k, v from ORIGINAL cluster centers (concurrent thread partitions)
    if (t < 128)                 mmr<64, 64, 0>(scc, sw1, bk, sk, t);
    else if (t < 256)            mmr<64, 64, 0>(scc, sw2, bv, sv, t - 128);
    __syncthreads();

    // persistent weights (overwrite temps)
    stageW<64,  64 >(Wq,   swq,  t);
    stageW<192, 64 >(W_ih, swih, t);
    stageW<192, 64 >(W_hh, swhh, t);
    stageW<128, 64 >(W1,   sw1,  t);
    stageW<64,  128>(W2,   sw2,  t);
    __syncthreads();

    for (int it = 0; it < 3; it++) {
        // ---- q = LN(cc; cc_g, cc_b) @ Wq^T + bq
        lnw(scc, cc_g, cc_b, sxu, sred, t);
        mmr<64, 64, 0>(sxu, swq, bq, sq, t);
        __syncthreads();

        // ---- attn logits: attn[an][am] = k[an].q[am] / 8
        if (t < 100) {
            int an = t / 10, am = t % 10;
            const float* kr = sk + an * D;
            const float* qr = sq + am * D;
            float ax = 0.f, ay = 0.f, az = 0.f, aw = 0.f;
            #pragma unroll
            for (int j = 0; j < D; j += 4) {
                float4 kv = *(const float4*)(kr + j);
                float4 qv = *(const float4*)(qr + j);
                ax = fmaf(kv.x, qv.x, ax);
                ay = fmaf(kv.y, qv.y, ay);
                az = fmaf(kv.z, qv.z, az);
                aw = fmaf(kv.w, qv.w, aw);
            }
            sattn[an * 10 + am] = ((ax + ay) + (az + aw)) * 0.125f;
        }
        __syncthreads();
        // softmax over axis 0 (rows an), column m = t
        if (t < 10) {
            float mx = -1e30f;
            #pragma unroll
            for (int a = 0; a < 10; a++) mx = fmaxf(mx, sattn[a * 10 + t]);
            float ss = 0.f;
            #pragma unroll
            for (int a = 0; a < 10; a++) {
                float e = expf(sattn[a * 10 + t] - mx);
                sattn[a * 10 + t] = e;
                ss += e;
            }
            float inv = 1.f / ss;
            #pragma unroll
            for (int a = 0; a < 10; a++)
                sattn[a * 10 + t] = sattn[a * 10 + t] * inv + 1e-8f;
        }
        __syncthreads();
        // renormalize rows (axis -1), row an = t
        if (t < 10) {
            float ss = 0.f;
            #pragma unroll
            for (int m = 0; m < 10; m++) ss += sattn[t * 10 + m];
            float inv = 1.f / ss;
            #pragma unroll
            for (int m = 0; m < 10; m++) sattn[t * 10 + m] *= inv;
        }
        __syncthreads();
        // updates = attn @ v  -> sxu
        {
            float u = 0.f;
            #pragma unroll
            for (int m = 0; m < 10; m++)
                u = fmaf(sattn[n * 10 + m], sv[m * D + ii], u);
            sxu[t] = u;
        }
        __syncthreads();

        // ---- GRU gates (gi from updates, gh from cc_prev; independent)
        mmr<192, 64, 0>(sxu, swih, b_ih, sgi, t);
        mmr<192, 64, 0>(scc, swhh, b_hh, sgh, t);
        __syncthreads();
        {
            float ir  = sgi[n * 192 + ii];
            float iz  = sgi[n * 192 + 64 + ii];
            float in_ = sgi[n * 192 + 128 + ii];
            float hr  = sgh[n * 192 + ii];
            float hz  = sgh[n * 192 + 64 + ii];
            float hn  = sgh[n * 192 + 128 + ii];
            float r  = 1.f / (1.f + expf(-(ir + hr)));
            float z  = 1.f / (1.f + expf(-(iz + hz)));
            float nn = tanhf(in_ + r * hn);
            scc[t] = (1.f - z) * nn + z * scc[t];
        }
        __syncthreads();

        // ---- residual MLP: cc += relu(LN(cc) @ W1^T + b1) @ W2^T + b2
        lnw(scc, ln_g, ln_b, sxu, sred, t);
        mmr<128, 64, 1>(sxu, sw1, b1, sgi, t);   // h1 [10,128]
        __syncthreads();
        mmr<64, 128, 0>(sgi, sw2, b2, sgh, t);   // delta [10,64]
        __syncthreads();
        scc[t] += sgh[t];
        __syncthreads();
    }

    g_cc[t] = scc[t];
}

// ---------------------------------------------------------------------------
// Kernel B: per-slot 2-layer MLP + max over 10 clusters. One block/slot.
// cp.async staging: Wb latency hidden behind stage-1 compute.
// ---------------------------------------------------------------------------
__device__ __forceinline__ void cp_async16(float* dst_smem, const float4* src) {
    unsigned int dst = (unsigned int)__cvta_generic_to_shared(dst_smem);
    asm volatile("cp.async.cg.shared.global [%0], [%1], 16;" :: "r"(dst), "l"(src));
}

__global__ void __launch_bounds__(128)
mlp_kernel(const float* __restrict__ Wa, const float* __restrict__ ba,
           const float* __restrict__ Wb, const float* __restrict__ bb,
           float* __restrict__ out) {
    __shared__ float sWa[64 * 68];
    __shared__ float sWb[64 * 68];
    __shared__ __align__(16) float scc[NC * D];
    __shared__ float sh [NC * D];
    __shared__ float smax[128];

    const int s = blockIdx.x;
    const int t = threadIdx.x;
    const int i = t & 63;
    const int g = t >> 6;
    const size_t base = (size_t)s * (D * D);

    const float4* ga = (const float4*)(Wa + base);
    const float4* gb = (const float4*)(Wb + base);

    // async stage Wa (first group) then Wb (second group) — wait for Wa only
    // before stage-1 compute; Wb arrives under that compute.
    #pragma unroll
    for (int p = 0; p < 8; p++) {
        int f = t + p * 128;
        int r = f >> 4;
        int c = (f & 15) << 2;
        cp_async16(sWa + r * 68 + c, ga + f);
    }
    asm volatile("cp.async.commit_group;");
    #pragma unroll
    for (int p = 0; p < 8; p++) {
        int f = t + p * 128;
        int r = f >> 4;
        int c = (f & 15) << 2;
        cp_async16(sWb + r * 68 + c, gb + f);
    }
    asm volatile("cp.async.commit_group;");

    float bav = ba[(s << 6) + i];
    float bbv = bb[(s << 6) + i];
    #pragma unroll
    for (int p = t; p < 160; p += 128)
        ((float4*)scc)[p] = ((const float4*)g_cc)[p];

    asm volatile("cp.async.wait_group 1;" ::: "memory");
    __syncthreads();

    // ---- stage 1: h[nn][i] = relu(Wa[i,:] . cc[nn,:] + ba[i]) for 5 nn
    {
        const float* wr = sWa + i * 68;
        const float* cb = scc + g * 5 * D;
        float a0 = 0.f, a1 = 0.f, a2 = 0.f, a3 = 0.f, a4 = 0.f;
        #pragma unroll
        for (int j = 0; j < D; j += 4) {
            float4 w  = *(const float4*)(wr + j);
            float4 c0 = *(const float4*)(cb + j);
            float4 c1 = *(const float4*)(cb + D + j);
            float4 c2 = *(const float4*)(cb + 2 * D + j);
            float4 c3 = *(const float4*)(cb + 3 * D + j);
            float4 c4 = *(const float4*)(cb + 4 * D + j);
            a0 = fmaf(w.x, c0.x, fmaf(w.y, c0.y, fmaf(w.z, c0.z, fmaf(w.w, c0.w, a0))));
            a1 = fmaf(w.x, c1.x, fmaf(w.y, c1.y, fmaf(w.z, c1.z, fmaf(w.w, c1.w, a1))));
            a2 = fmaf(w.x, c2.x, fmaf(w.y, c2.y, fmaf(w.z, c2.z, fmaf(w.w, c2.w, a2))));
            a3 = fmaf(w.x, c3.x, fmaf(w.y, c3.y, fmaf(w.z, c3.z, fmaf(w.w, c3.w, a3))));
            a4 = fmaf(w.x, c4.x, fmaf(w.y, c4.y, fmaf(w.z, c4.z, fmaf(w.w, c4.w, a4))));
        }
        int n0 = g * 5;
        sh[(n0 + 0) * D + i] = fmaxf(a0 + bav, 0.f);
        sh[(n0 + 1) * D + i] = fmaxf(a1 + bav, 0.f);
        sh[(n0 + 2) * D + i] = fmaxf(a2 + bav, 0.f);
        sh[(n0 + 3) * D + i] = fmaxf(a3 + bav, 0.f);
        sh[(n0 + 4) * D + i] = fmaxf(a4 + bav, 0.f);
    }
    asm volatile("cp.async.wait_group 0;" ::: "memory");
    __syncthreads();

    // ---- stage 2: out[nn][i] = Wb[i,:] . h[nn,:] + bb[i], max over nn
    {
        const float* wr = sWb + i * 68;
        const float* hb = sh + g * 5 * D;
        float a0 = 0.f, a1 = 0.f, a2 = 0.f, a3 = 0.f, a4 = 0.f;
        #pragma unroll
        for (int j = 0; j < D; j += 4) {
            float4 w  = *(const float4*)(wr + j);
            float4 c0 = *(const float4*)(hb + j);
            float4 c1 = *(const float4*)(hb + D + j);
            float4 c2 = *(const float4*)(hb + 2 * D + j);
            float4 c3 = *(const float4*)(hb + 3 * D + j);
            float4 c4 = *(const float4*)(hb + 4 * D + j);
            a0 = fmaf(w.x, c0.x, fmaf(w.y, c0.y, fmaf(w.z, c0.z, fmaf(w.w, c0.w, a0))));
            a1 = fmaf(w.x, c1.x, fmaf(w.y, c1.y, fmaf(w.z, c1.z, fmaf(w.w, c1.w, a1))));
            a2 = fmaf(w.x, c2.x, fmaf(w.y, c2.y, fmaf(w.z, c2.z, fmaf(w.w, c2.w, a2))));
            a3 = fmaf(w.x, c3.x, fmaf(w.y, c3.y, fmaf(w.z, c3.z, fmaf(w.w, c3.w, a3))));
            a4 = fmaf(w.x, c4.x, fmaf(w.y, c4.y, fmaf(w.z, c4.z, fmaf(w.w, c4.w, a4))));
        }
        smax[t] = fmaxf(fmaxf(fmaxf(a0, a1), fmaxf(a2, a3)), a4) + bbv;
    }
    __syncthreads();
    if (g == 0) out[(s << 6) + i] = fmaxf(smax[i], smax[64 + i]);
}

// ---------------------------------------------------------------------------
extern "C" void kernel_launch(void* const* d_in, const int* in_sizes, int n_in,
                              void* d_out, int out_size) {
    const float* cc0  = (const float*)d_in[0];
    const float* Wk   = (const float*)d_in[1];
    const float* bk   = (const float*)d_in[2];
    const float* Wq   = (const float*)d_in[3];
    const float* bq   = (const float*)d_in[4];
    const float* Wv   = (const float*)d_in[5];
    const float* bv   = (const float*)d_in[6];
    const float* cc_g = (const float*)d_in[7];
    const float* cc_b = (const float*)d_in[8];
    const float* W_ih = (const float*)d_in[9];
    const float* W_hh = (const float*)d_in[10];
    const float* b_ih = (const float*)d_in[11];
    const float* b_hh = (const float*)d_in[12];
    const float* ln_g = (const float*)d_in[13];
    const float* ln_b = (const float*)d_in[14];
    const float* W1   = (const float*)d_in[15];
    const float* b1   = (const float*)d_in[16];
    const float* W2   = (const float*)d_in[17];
    const float* b2   = (const float*)d_in[18];
    const float* Wa   = (const float*)d_in[19];
    const float* ba   = (const float*)d_in[20];
    const float* Wb   = (const float*)d_in[21];
    const float* bb   = (const float*)d_in[22];
    float* out = (float*)d_out;

    cudaFuncSetAttribute(iter_kernel,
                         cudaFuncAttributeMaxDynamicSharedMemorySize,
                         SMEM_A_BYTES);

    iter_kernel<<<1, 640, SMEM_A_BYTES>>>(cc0, Wk, bk, Wq, bq, Wv, bv,
                                          cc_g, cc_b, W_ih, W_hh, b_ih, b_hh,
                                          ln_g, ln_b, W1, b1, W2, b2);
    mlp_kernel<<<NS, 128>>>(Wa, ba, Wb, bb, out);
}